// round 7
// baseline (speedup 1.0000x reference)
#include <cuda_runtime.h>

// actions: [B=4096, T=256, A=64] fp32
// out[b,t,a] = x[b,0,a] + sum_{s=1..t} clip(x[b,s,a]-x[b,s-1,a], -0.5, 0.5)
//
// Warp-independent segmented scan — NO barriers, NO shared memory.
//   1 block (256 thr = 8 warps) per b-row.
//   Warp w owns a4 columns {2w, 2w+1}; lane = seg*2 + (a4&1), seg in 0..15.
//   Each lane scans SEGLEN=16 timesteps locally; segment totals combined via
//   a 4-step shfl_up scan (stride 2); x[b,0,:] comes from a lane broadcast.
//   Exactly 1 global load + 1 store per element (+1 L2-hit boundary re-read).

#define A4     16
#define SEGLEN 16
#define TSTEPS 256

__device__ __forceinline__ float clip05(float d) {
    return fminf(fmaxf(d, -0.5f), 0.5f);
}
__device__ __forceinline__ float4 f4add(float4 a, float4 b) {
    return make_float4(a.x + b.x, a.y + b.y, a.z + b.z, a.w + b.w);
}
__device__ __forceinline__ float4 f4sub(float4 a, float4 b) {
    return make_float4(a.x - b.x, a.y - b.y, a.z - b.z, a.w - b.w);
}
__device__ __forceinline__ float4 shfl_up4(float4 v, int d) {
    float4 r;
    r.x = __shfl_up_sync(0xffffffffu, v.x, d);
    r.y = __shfl_up_sync(0xffffffffu, v.y, d);
    r.z = __shfl_up_sync(0xffffffffu, v.z, d);
    r.w = __shfl_up_sync(0xffffffffu, v.w, d);
    return r;
}
__device__ __forceinline__ float4 shfl4(float4 v, int src) {
    float4 r;
    r.x = __shfl_sync(0xffffffffu, v.x, src);
    r.y = __shfl_sync(0xffffffffu, v.y, src);
    r.z = __shfl_sync(0xffffffffu, v.z, src);
    r.w = __shfl_sync(0xffffffffu, v.w, src);
    return r;
}

__global__ void __launch_bounds__(256, 2) smoothness_warp_scan_kernel(
    const float4* __restrict__ x, float4* __restrict__ y)
{
    const int b    = blockIdx.x;
    const int tid  = threadIdx.x;
    const int w    = tid >> 5;        // warp 0..7
    const int lane = tid & 31;
    const int seg  = lane >> 1;       // 0..15
    const int h    = lane & 1;        // which of the warp's 2 a4 columns
    const int a4   = (w << 1) | h;    // 0..15

    const float4* xb = x + (long)b * (TSTEPS * A4);
    float4*       yb = y + (long)b * (TSTEPS * A4);
    const int t0 = seg * SEGLEN;

    // Batch 16 independent loads (+ boundary) for MLP.
    float4 c[SEGLEN];
    #pragma unroll
    for (int j = 0; j < SEGLEN; ++j)
        c[j] = xb[(t0 + j) * A4 + a4];
    float4 prev = (seg > 0) ? xb[(t0 - 1) * A4 + a4] : c[0];

    const float4 x0 = c[0];           // meaningful on seg==0 lanes only

    // Local prefix of clipped diffs, in place.
    float4 acc = make_float4(0.f, 0.f, 0.f, 0.f);
    #pragma unroll
    for (int j = 0; j < SEGLEN; ++j) {
        float4 cur = c[j];
        if (seg == 0 && j == 0) {
            c[0] = acc;               // local prefix at t=0 is 0
            prev = cur;
            continue;
        }
        acc.x += clip05(cur.x - prev.x);
        acc.y += clip05(cur.y - prev.y);
        acc.z += clip05(cur.z - prev.z);
        acc.w += clip05(cur.w - prev.w);
        prev = cur;
        c[j] = acc;
    }

    // Inclusive scan of segment totals across lanes (stride 2 = same column).
    float4 inc = acc;
    #pragma unroll
    for (int d = 2; d < 32; d <<= 1) {
        float4 up = shfl_up4(inc, d);
        if (lane >= d) inc = f4add(inc, up);
    }
    // Exclusive prefix + base x[b,0,a4] broadcast from lane h (seg 0, same col).
    float4 offset = f4add(f4sub(inc, acc), shfl4(x0, h));

    // Add offset and store.
    #pragma unroll
    for (int j = 0; j < SEGLEN; ++j)
        yb[(t0 + j) * A4 + a4] = f4add(offset, c[j]);
}

extern "C" void kernel_launch(void* const* d_in, const int* in_sizes, int n_in,
                              void* d_out, int out_size) {
    const float4* x = (const float4*)d_in[0];
    float4* y = (float4*)d_out;
    smoothness_warp_scan_kernel<<<4096, 256>>>(x, y);
}

// round 8
// speedup vs baseline: 1.0381x; 1.0381x over previous
#include <cuda_runtime.h>

// actions: [B=4096, T=256, A=64] fp32
// out[b,t,a] = x[b,0,a] + sum_{s=1..t} clip(x[b,s,a]-x[b,s-1,a], -0.5, 0.5)
//
// R2 structure (best known: 82.5us, DRAM 77%) + write-through stores.
//   1 block per b. 256 threads = 16 t-segments x 16 a4-columns, SEGLEN=16.
//   Single __syncthreads. Boundary re-read from global (L2 hit).
//   Stores use __stwt: streaming output never re-read -> skip L2 dirty
//   residency, reduce LTS eviction pressure against the read stream.

#define A4     16   // float4 per A-dim
#define SEGS   16
#define SEGLEN 16
#define TSTEPS 256

__device__ __forceinline__ float clip05(float d) {
    return fminf(fmaxf(d, -0.5f), 0.5f);
}

__device__ __forceinline__ float4 f4add(float4 a, float4 b) {
    return make_float4(a.x + b.x, a.y + b.y, a.z + b.z, a.w + b.w);
}

__global__ void __launch_bounds__(256, 2) smoothness_scan_kernel(
    const float4* __restrict__ x, float4* __restrict__ y)
{
    const int b   = blockIdx.x;
    const int tid = threadIdx.x;
    const int seg = tid >> 4;     // 0..15
    const int a4  = tid & 15;     // 0..15

    const float4* xb = x + (long)b * (TSTEPS * A4);
    float4*       yb = y + (long)b * (TSTEPS * A4);

    __shared__ float4 s_sum[SEGS][A4];   // per-segment clipped-diff totals
    __shared__ float4 s_x0[A4];          // x[b, 0, :]

    const int t0 = seg * SEGLEN;

    // Batch all loads up front for memory-level parallelism (~17 in flight).
    float4 c[SEGLEN];
    #pragma unroll
    for (int j = 0; j < SEGLEN; ++j)
        c[j] = xb[(t0 + j) * A4 + a4];

    float4 prev;
    if (seg > 0)
        prev = xb[(t0 - 1) * A4 + a4];   // boundary element (L2-hit re-read)

    // Local prefix of clipped diffs within the segment, in-place into c[].
    float4 acc = make_float4(0.f, 0.f, 0.f, 0.f);
    int jstart = 0;
    if (seg == 0) {
        s_x0[a4] = c[0];
        prev = c[0];
        c[0] = acc;                      // local prefix at t=0 is 0
        jstart = 1;
    }
    #pragma unroll
    for (int j = 0; j < SEGLEN; ++j) {
        if (j < jstart) continue;
        float4 cur = c[j];
        acc.x += clip05(cur.x - prev.x);
        acc.y += clip05(cur.y - prev.y);
        acc.z += clip05(cur.z - prev.z);
        acc.w += clip05(cur.w - prev.w);
        prev = cur;
        c[j] = acc;
    }
    s_sum[seg][a4] = acc;
    __syncthreads();                     // single barrier

    // Exclusive prefix over segment totals + base x[b,0,:].
    float4 offset = s_x0[a4];
    #pragma unroll
    for (int k = 0; k < SEGS; ++k) {
        if (k < seg) offset = f4add(offset, s_sum[k][a4]);
    }

    // Add offset and store write-through (no L2 dirty residency).
    #pragma unroll
    for (int j = 0; j < SEGLEN; ++j)
        __stwt(&yb[(t0 + j) * A4 + a4], f4add(offset, c[j]));
}

extern "C" void kernel_launch(void* const* d_in, const int* in_sizes, int n_in,
                              void* d_out, int out_size) {
    const float4* x = (const float4*)d_in[0];
    float4* y = (float4*)d_out;
    smoothness_scan_kernel<<<4096, 256>>>(x, y);
}

// round 9
// speedup vs baseline: 1.0429x; 1.0046x over previous
#include <cuda_runtime.h>

// actions: [B=4096, T=256, A=64] fp32
// out[b,t,a] = x[b,0,a] + sum_{s=1..t} clip(x[b,s,a]-x[b,s-1,a], -0.5, 0.5)
//
// Best-known shape (R2/R8): 1 block per b, 256 thr = 16 t-segments x 16
// a4-cols, SEGLEN=16, single barrier. This revision:
//   - boundary load hoisted FIRST (consumed first in the prefix loop)
//   - __ldcg reads (L2-only; data has zero reuse, skip L1 insertion)
//   - __stwt writes (write-through; no L2 dirty residency for the
//     never-re-read output stream) — kept from R8, best measured.

#define A4     16   // float4 per A-dim
#define SEGS   16
#define SEGLEN 16
#define TSTEPS 256

__device__ __forceinline__ float clip05(float d) {
    return fminf(fmaxf(d, -0.5f), 0.5f);
}

__device__ __forceinline__ float4 f4add(float4 a, float4 b) {
    return make_float4(a.x + b.x, a.y + b.y, a.z + b.z, a.w + b.w);
}

__global__ void __launch_bounds__(256, 2) smoothness_scan_kernel(
    const float4* __restrict__ x, float4* __restrict__ y)
{
    const int b   = blockIdx.x;
    const int tid = threadIdx.x;
    const int seg = tid >> 4;     // 0..15
    const int a4  = tid & 15;     // 0..15

    const float4* xb = x + (long)b * (TSTEPS * A4);
    float4*       yb = y + (long)b * (TSTEPS * A4);

    __shared__ float4 s_sum[SEGS][A4];   // per-segment clipped-diff totals
    __shared__ float4 s_x0[A4];          // x[b, 0, :]

    const int t0 = seg * SEGLEN;

    // Boundary load FIRST (it is the first value consumed), then the batch.
    float4 prev;
    if (seg > 0)
        prev = __ldcg(&xb[(t0 - 1) * A4 + a4]);   // L2-hit re-read

    float4 c[SEGLEN];
    #pragma unroll
    for (int j = 0; j < SEGLEN; ++j)
        c[j] = __ldcg(&xb[(t0 + j) * A4 + a4]);

    // Local prefix of clipped diffs within the segment, in-place into c[].
    float4 acc = make_float4(0.f, 0.f, 0.f, 0.f);
    int jstart = 0;
    if (seg == 0) {
        s_x0[a4] = c[0];
        prev = c[0];
        c[0] = acc;                      // local prefix at t=0 is 0
        jstart = 1;
    }
    #pragma unroll
    for (int j = 0; j < SEGLEN; ++j) {
        if (j < jstart) continue;
        float4 cur = c[j];
        acc.x += clip05(cur.x - prev.x);
        acc.y += clip05(cur.y - prev.y);
        acc.z += clip05(cur.z - prev.z);
        acc.w += clip05(cur.w - prev.w);
        prev = cur;
        c[j] = acc;
    }
    s_sum[seg][a4] = acc;
    __syncthreads();                     // single barrier

    // Exclusive prefix over segment totals + base x[b,0,:].
    float4 offset = s_x0[a4];
    #pragma unroll
    for (int k = 0; k < SEGS; ++k) {
        if (k < seg) offset = f4add(offset, s_sum[k][a4]);
    }

    // Add offset and store write-through.
    #pragma unroll
    for (int j = 0; j < SEGLEN; ++j)
        __stwt(&yb[(t0 + j) * A4 + a4], f4add(offset, c[j]));
}

extern "C" void kernel_launch(void* const* d_in, const int* in_sizes, int n_in,
                              void* d_out, int out_size) {
    const float4* x = (const float4*)d_in[0];
    float4* y = (float4*)d_out;
    smoothness_scan_kernel<<<4096, 256>>>(x, y);
}